// round 11
// baseline (speedup 1.0000x reference)
#include <cuda_runtime.h>
#include <cuda_bf16.h>
#include <cstdint>

#define IN_CH 256
#define OUT_CH 128
#define MAX_NODES 100000
#define MAX_EDGES 1600000
#define SCAN_B 1024

__device__ float g_h[MAX_NODES * OUT_CH];   // x @ W
__device__ float g_dinv[MAX_NODES];         // (deg incl self)^-1/2
__device__ int   g_cnt[MAX_NODES];          // in-degree (excl self)
__device__ int   g_off[MAX_NODES];          // CSR row offsets
__device__ int   g_cur[MAX_NODES];          // fill cursors
__device__ int   g_esrc[MAX_EDGES];         // edge sources grouped by dest
__device__ int   g_bsum[128];
__device__ int   g_bbase[128];

// ===================== small pipeline kernels =====================
__global__ void zero_kernel(int n) {
    int i = blockIdx.x * blockDim.x + threadIdx.x;
    if (i < n) g_cnt[i] = 0;
}
__global__ void deg_kernel(const int* __restrict__ ei, int nE) {
    int e = blockIdx.x * blockDim.x + threadIdx.x;
    if (e < nE) atomicAdd(&g_cnt[ei[nE + e]], 1);
}
// scanA + fused dinv
__global__ void scanA_kernel(int n) {
    __shared__ int s[SCAN_B];
    int i = blockIdx.x * SCAN_B + threadIdx.x;
    int v = (i < n) ? g_cnt[i] : 0;
    s[threadIdx.x] = v;
    __syncthreads();
    for (int o = 1; o < SCAN_B; o <<= 1) {
        int t = (threadIdx.x >= o) ? s[threadIdx.x - o] : 0;
        __syncthreads();
        s[threadIdx.x] += t;
        __syncthreads();
    }
    if (i < n) {
        g_off[i] = s[threadIdx.x] - v;
        g_dinv[i] = rsqrtf((float)(v + 1));   // fused: deg incl self-loop
    }
    if (threadIdx.x == SCAN_B - 1) g_bsum[blockIdx.x] = s[SCAN_B - 1];
}
__global__ void scanB_kernel(int nb) {
    __shared__ int s[128];
    int t = threadIdx.x;
    int v = (t < nb) ? g_bsum[t] : 0;
    s[t] = v;
    __syncthreads();
    for (int o = 1; o < 128; o <<= 1) {
        int u = (t >= o) ? s[t - o] : 0;
        __syncthreads();
        s[t] += u;
        __syncthreads();
    }
    if (t < nb) g_bbase[t] = s[t] - v;
}
__global__ void scanC_kernel(int n) {
    int i = blockIdx.x * blockDim.x + threadIdx.x;
    if (i < n) {
        int o = g_off[i] + g_bbase[i / SCAN_B];
        g_off[i] = o;
        g_cur[i] = o;
    }
}
__global__ void fill_kernel(const int* __restrict__ ei, int nE) {
    int e = blockIdx.x * blockDim.x + threadIdx.x;
    if (e < nE) {
        int d = ei[nE + e];
        g_esrc[atomicAdd(&g_cur[d], 1)] = ei[e];
    }
}

// ===================== tf32 mma.sync GEMM with cp.async pipeline =====================
// CTA: 128x128 tile, K=256 in 16 chunks of 16, double-buffered cp.async.
// 8 warps (4x2): warp tile 32x64. fp32 bits fed as tf32 (truncation).
#define KC 16
#define A_STR 20     // words; frag bank = (lq*20+lr) mod 32 -> all 32 distinct
#define B_STR 136    // words; frag bank = (lr*8+lq) mod 32 -> all distinct
#define EPI_STR 68
#define BUF_W 4736   // words per buffer: A 128*20=2560 + B 16*136=2176

__device__ __forceinline__ void cp16(uint32_t saddr, const void* g, int src_sz) {
    asm volatile("cp.async.cg.shared.global [%0], [%1], 16, %2;"
                 :: "r"(saddr), "l"(g), "r"(src_sz));
}
#define CP_COMMIT() asm volatile("cp.async.commit_group;" ::: "memory")
#define CP_WAIT1()  asm volatile("cp.async.wait_group 1;" ::: "memory")
#define CP_WAIT0()  asm volatile("cp.async.wait_group 0;" ::: "memory")

__device__ __forceinline__ uint32_t smem_u32(const void* p) {
    uint32_t a;
    asm("{ .reg .u64 t; cvta.to.shared.u64 t, %1; cvt.u32.u64 %0, t; }" : "=r"(a) : "l"(p));
    return a;
}

__global__ __launch_bounds__(256) void gemm_mma_kernel(const float* __restrict__ x,
                                                       const float* __restrict__ W, int n) {
    __shared__ __align__(16) uint32_t sbuf[2 * BUF_W];   // 37888 B; epi reuses 8704 w
    uint32_t sbase = smem_u32(sbuf);

    int tid = threadIdx.x;
    int wid = tid >> 5;
    int lane = tid & 31;
    int wm = wid & 3;
    int wn = wid >> 2;
    int r0 = blockIdx.x * 128;

    float acc[2][8][4];
#pragma unroll
    for (int mt = 0; mt < 2; ++mt)
#pragma unroll
        for (int nt = 0; nt < 8; ++nt)
#pragma unroll
            for (int q = 0; q < 4; ++q) acc[mt][nt][q] = 0.0f;

    int lq = lane >> 2;
    int lr = lane & 3;

    // stage chunk -> buffer sel (2 A items + 2 B items per thread)
    auto stage = [&](int chunk, int sel) {
        int k0 = chunk * KC;
        uint32_t abase = sbase + (uint32_t)sel * BUF_W * 4;
        uint32_t bbase = abase + 2560 * 4;
#pragma unroll
        for (int j = 0; j < 2; ++j) {
            int item = tid + 256 * j;            // 0..511
            int row = item >> 2, quad = item & 3;
            int grow = r0 + row;
            int ok = (grow < n) ? 16 : 0;
            if (grow >= n) grow = n - 1;
            cp16(abase + (uint32_t)(row * A_STR + quad * 4) * 4,
                 &x[(size_t)grow * IN_CH + k0 + quad * 4], ok);
        }
#pragma unroll
        for (int j = 0; j < 2; ++j) {
            int item = tid + 256 * j;            // 0..511
            int kk = item >> 5, n4 = item & 31;
            cp16(bbase + (uint32_t)(kk * B_STR + n4 * 4) * 4,
                 &W[(size_t)(k0 + kk) * OUT_CH + n4 * 4], 16);
        }
        CP_COMMIT();
    };

    stage(0, 0);
    for (int chunk = 0; chunk < 16; ++chunk) {
        int sel = chunk & 1;
        if (chunk < 15) { stage(chunk + 1, sel ^ 1); CP_WAIT1(); }
        else            { CP_WAIT0(); }
        __syncthreads();
        const uint32_t* As = sbuf + sel * BUF_W;
        const uint32_t* Bs = As + 2560;
#pragma unroll
        for (int ks = 0; ks < 2; ++ks) {
            int kk = ks * 8 + lr;
            uint32_t a[2][4];
#pragma unroll
            for (int mt = 0; mt < 2; ++mt) {
                int row = wm * 32 + mt * 16 + lq;
                a[mt][0] = As[row * A_STR + kk];
                a[mt][1] = As[(row + 8) * A_STR + kk];
                a[mt][2] = As[row * A_STR + kk + 4];
                a[mt][3] = As[(row + 8) * A_STR + kk + 4];
            }
            uint32_t bf[8][2];
#pragma unroll
            for (int nt = 0; nt < 8; ++nt) {
                int col = wn * 64 + nt * 8 + lq;
                bf[nt][0] = Bs[kk * B_STR + col];
                bf[nt][1] = Bs[(kk + 4) * B_STR + col];
            }
#pragma unroll
            for (int mt = 0; mt < 2; ++mt)
#pragma unroll
                for (int nt = 0; nt < 8; ++nt)
                    asm volatile(
                        "mma.sync.aligned.m16n8k8.row.col.f32.tf32.tf32.f32 "
                        "{%0,%1,%2,%3},{%4,%5,%6,%7},{%8,%9},{%0,%1,%2,%3};"
                        : "+f"(acc[mt][nt][0]), "+f"(acc[mt][nt][1]),
                          "+f"(acc[mt][nt][2]), "+f"(acc[mt][nt][3])
                        : "r"(a[mt][0]), "r"(a[mt][1]), "r"(a[mt][2]), "r"(a[mt][3]),
                          "r"(bf[nt][0]), "r"(bf[nt][1]));
        }
        __syncthreads();
    }

    // epilogue: two 64-col halves through padded smem, then coalesced float4 out
    float* s = (float*)sbuf;
    for (int h = 0; h < 2; ++h) {
        if (wn == h) {
#pragma unroll
            for (int mt = 0; mt < 2; ++mt)
#pragma unroll
                for (int nt = 0; nt < 8; ++nt) {
                    int row = wm * 32 + mt * 16 + lq;
                    int col = nt * 8 + 2 * lr;
                    s[row * EPI_STR + col]           = acc[mt][nt][0];
                    s[row * EPI_STR + col + 1]       = acc[mt][nt][1];
                    s[(row + 8) * EPI_STR + col]     = acc[mt][nt][2];
                    s[(row + 8) * EPI_STR + col + 1] = acc[mt][nt][3];
                }
        }
        __syncthreads();
#pragma unroll
        for (int j = 0; j < 8; ++j) {
            int item = tid + 256 * j;            // 0..2047
            int orow = item >> 4, c4 = item & 15;
            if (r0 + orow < n)
                *(float4*)&g_h[(size_t)(r0 + orow) * OUT_CH + h * 64 + c4 * 4] =
                    *(float4*)&s[orow * EPI_STR + c4 * 4];
        }
        __syncthreads();
    }
}

// ===================== gather + finalize: cooperative src prefetch =====================
__global__ __launch_bounds__(256) void gather_kernel(const float* __restrict__ b,
                                                     float* __restrict__ out, int n) {
    int node = (blockIdx.x * blockDim.x + threadIdx.x) >> 5;
    int lane = threadIdx.x & 31;
    if (node >= n) return;

    float di = g_dinv[node];
    float4 hv = *(const float4*)&g_h[(size_t)node * OUT_CH + lane * 4];
    float4 bv = *(const float4*)&b[lane * 4];
    float s2 = di * di;
    float4 acc = make_float4(fmaf(hv.x, s2, bv.x), fmaf(hv.y, s2, bv.y),
                             fmaf(hv.z, s2, bv.z), fmaf(hv.w, s2, bv.w));

    int base = g_off[node];
    int cnt  = g_cnt[node];
    for (int j0 = 0; j0 < cnt; j0 += 32) {
        int m = min(32, cnt - j0);
        // lanes cooperatively load srcs + weights for up to 32 edges
        int src = 0;
        float wl = 0.0f;
        if (lane < m) {
            src = g_esrc[base + j0 + lane];
            wl  = g_dinv[src] * di;
        }
        // 2-deep pipelined accumulation
        int s0 = __shfl_sync(0xffffffffu, src, 0);
        float4 nv = *(const float4*)&g_h[(size_t)s0 * OUT_CH + lane * 4];
        for (int j = 0; j < m; ++j) {
            float4 cv = nv;
            float w = __shfl_sync(0xffffffffu, wl, j);
            if (j + 1 < m) {
                int sn = __shfl_sync(0xffffffffu, src, j + 1);
                nv = *(const float4*)&g_h[(size_t)sn * OUT_CH + lane * 4];
            }
            acc.x = fmaf(cv.x, w, acc.x);
            acc.y = fmaf(cv.y, w, acc.y);
            acc.z = fmaf(cv.z, w, acc.z);
            acc.w = fmaf(cv.w, w, acc.w);
        }
    }

    float mn = fminf(fminf(acc.x, acc.y), fminf(acc.z, acc.w));
    float mx = fmaxf(fmaxf(acc.x, acc.y), fmaxf(acc.z, acc.w));
#pragma unroll
    for (int o = 16; o; o >>= 1) {
        mn = fminf(mn, __shfl_xor_sync(0xffffffffu, mn, o));
        mx = fmaxf(mx, __shfl_xor_sync(0xffffffffu, mx, o));
    }
    float inv = 1.0f / (mx - mn);
    float4 z = make_float4((acc.x - mn) * inv, (acc.y - mn) * inv,
                           (acc.z - mn) * inv, (acc.w - mn) * inv);
    float ss = z.x * z.x + z.y * z.y + z.z * z.z + z.w * z.w;
#pragma unroll
    for (int o = 16; o; o >>= 1) ss += __shfl_xor_sync(0xffffffffu, ss, o);
    float rn = 1.0f / fmaxf(sqrtf(ss), 1e-12f);
    z.x *= rn; z.y *= rn; z.z *= rn; z.w *= rn;
    *(float4*)&out[(size_t)node * OUT_CH + lane * 4] = z;
}

// ===================== launch =====================
extern "C" void kernel_launch(void* const* d_in, const int* in_sizes, int n_in,
                              void* d_out, int out_size) {
    const float* x  = (const float*)d_in[0];
    const int*   ei = (const int*)d_in[1];     // int32
    const float* W  = (const float*)d_in[2];
    const float* b  = (const float*)d_in[3];
    float*       out = (float*)d_out;

    int n  = in_sizes[0] / IN_CH;   // 100000
    int nE = in_sizes[1] / 2;       // 1600000
    int nb = (n + SCAN_B - 1) / SCAN_B;

    zero_kernel<<<(n + 255) / 256, 256>>>(n);
    deg_kernel<<<(nE + 255) / 256, 256>>>(ei, nE);
    scanA_kernel<<<nb, SCAN_B>>>(n);
    scanB_kernel<<<1, 128>>>(nb);
    scanC_kernel<<<(n + 255) / 256, 256>>>(n);
    fill_kernel<<<(nE + 255) / 256, 256>>>(ei, nE);
    gemm_mma_kernel<<<(n + 127) / 128, 256>>>(x, W, n);
    gather_kernel<<<(n * 32 + 255) / 256, 256>>>(b, out, n);
}